// round 4
// baseline (speedup 1.0000x reference)
#include <cuda_runtime.h>
#include <math.h>
#include <stdint.h>

// Causal SDPA, flash-attention-2 style, TF32 mma.sync (fallback HMMA on sm_103a).
// B=2, S=4096, NH=16, HD=64, fp32 in/out. Layout [B, S, NH, HD].
#define BATCH    2
#define SEQLEN   4096
#define NHEADS   16
#define HDIM     64
#define BM       64        // q rows per CTA
#define BN       64        // kv cols per tile
#define LDP      68        // padded smem row stride (floats): conflict-free frags, 16B aligned
#define NTHREADS 128       // 4 warps, one m16 row-band each

__device__ __forceinline__ uint32_t f2tf(float f) {
    uint32_t r;
    asm("cvt.rna.tf32.f32 %0, %1;" : "=r"(r) : "f"(f));
    return r;
}

__device__ __forceinline__ void mma_tf32(float* d, const uint32_t* a,
                                         const uint32_t* b, const float* c) {
    asm("mma.sync.aligned.m16n8k8.row.col.f32.tf32.tf32.f32 "
        "{%0,%1,%2,%3}, {%4,%5,%6,%7}, {%8,%9}, {%10,%11,%12,%13};\n"
        : "=f"(d[0]), "=f"(d[1]), "=f"(d[2]), "=f"(d[3])
        : "r"(a[0]), "r"(a[1]), "r"(a[2]), "r"(a[3]),
          "r"(b[0]), "r"(b[1]),
          "f"(c[0]), "f"(c[1]), "f"(c[2]), "f"(c[3]));
}

__global__ void __launch_bounds__(NTHREADS, 3)
fa_tf32_kernel(const float* __restrict__ Q, const float* __restrict__ K,
               const float* __restrict__ V, float* __restrict__ O)
{
    __shared__ float sK[BN * LDP];    // K tile [kv][hd]; reused as P [qrow][kv]
    __shared__ float sV[HDIM * LDP];  // V^T tile [hd][kv]

    const int qt   = (SEQLEN / BM - 1) - (int)blockIdx.x;  // heavy tiles first
    const int h    = blockIdx.y;
    const int b    = blockIdx.z;
    const int tid  = threadIdx.x;
    const int warp = tid >> 5;
    const int lane = tid & 31;
    const int g    = lane >> 2;   // groupID (row within m16 half)
    const int t4   = lane & 3;    // thread-in-group

    const int q0 = qt * BM;
    const size_t rowstride = (size_t)NHEADS * HDIM;  // 1024 floats per s-step
    const size_t base = (size_t)b * SEQLEN * rowstride + (size_t)h * HDIM;
    const float* Qb = Q + base;
    const float* Kb = K + base;
    const float* Vb = V + base;
    float*       Ob = O + base;

    // ---- Q fragments: m16k8 x 8 k-chunks, pre-scaled by 1/sqrt(HD), tf32 ----
    uint32_t qa[8][4];
    {
        const int r0 = q0 + warp * 16 + g;
        const float* q_r0 = Qb + (size_t)r0 * rowstride;
        const float* q_r1 = q_r0 + 8 * rowstride;
        const float scale = 0.125f;  // 1/sqrt(64)
        #pragma unroll
        for (int kc = 0; kc < 8; kc++) {
            const int c = kc * 8 + t4;
            qa[kc][0] = f2tf(q_r0[c]     * scale);
            qa[kc][1] = f2tf(q_r1[c]     * scale);
            qa[kc][2] = f2tf(q_r0[c + 4] * scale);
            qa[kc][3] = f2tf(q_r1[c + 4] * scale);
        }
    }

    // online-softmax state: two rows per thread (g and g+8)
    float m0 = -1e30f, m1 = -1e30f;
    float l0 = 0.f,    l1 = 0.f;
    float o[8][4];
    #pragma unroll
    for (int n = 0; n < 8; n++) { o[n][0] = o[n][1] = o[n][2] = o[n][3] = 0.f; }

    for (int kt = 0; kt <= qt; kt++) {
        const int k0 = kt * BN;
        __syncthreads();  // previous iteration's P/V reads done before restaging

        // ---- stage K (row-major, tf32) and V (transposed, tf32) ----
        {
            const float* Kt = Kb + (size_t)k0 * rowstride;
            const float* Vt = Vb + (size_t)k0 * rowstride;
            #pragma unroll
            for (int j = 0; j < 8; j++) {
                const int f  = tid + NTHREADS * j;   // 1024 float4s = 64 rows x 16
                const int rw = f >> 4;
                const int c4 = (f & 15) << 2;
                float4 kk = *(const float4*)(Kt + (size_t)rw * rowstride + c4);
                kk.x = __uint_as_float(f2tf(kk.x));
                kk.y = __uint_as_float(f2tf(kk.y));
                kk.z = __uint_as_float(f2tf(kk.z));
                kk.w = __uint_as_float(f2tf(kk.w));
                *(float4*)(&sK[rw * LDP + c4]) = kk;
                float4 vv = *(const float4*)(Vt + (size_t)rw * rowstride + c4);
                sV[(c4 + 0) * LDP + rw] = __uint_as_float(f2tf(vv.x));
                sV[(c4 + 1) * LDP + rw] = __uint_as_float(f2tf(vv.y));
                sV[(c4 + 2) * LDP + rw] = __uint_as_float(f2tf(vv.z));
                sV[(c4 + 3) * LDP + rw] = __uint_as_float(f2tf(vv.w));
            }
        }
        __syncthreads();

        // ---- S = Qs @ K^T  (m16 x n64 per warp) ----
        float sc[8][4];
        #pragma unroll
        for (int n = 0; n < 8; n++) { sc[n][0] = sc[n][1] = sc[n][2] = sc[n][3] = 0.f; }
        #pragma unroll
        for (int kc = 0; kc < 8; kc++) {
            #pragma unroll
            for (int n = 0; n < 8; n++) {
                uint32_t bf[2];
                bf[0] = __float_as_uint(sK[(n * 8 + g) * LDP + kc * 8 + t4]);
                bf[1] = __float_as_uint(sK[(n * 8 + g) * LDP + kc * 8 + t4 + 4]);
                mma_tf32(sc[n], qa[kc], bf, sc[n]);
            }
        }

        // ---- causal mask on the diagonal tile ----
        if (kt == qt) {
            const int r0 = q0 + warp * 16 + g;
            #pragma unroll
            for (int n = 0; n < 8; n++) {
                const int c = k0 + n * 8 + 2 * t4;
                if (c     > r0)     sc[n][0] = -1e30f;
                if (c + 1 > r0)     sc[n][1] = -1e30f;
                if (c     > r0 + 8) sc[n][2] = -1e30f;
                if (c + 1 > r0 + 8) sc[n][3] = -1e30f;
            }
        }

        // ---- online softmax (rows g, g+8) ----
        float mn0 = m0, mn1 = m1;
        #pragma unroll
        for (int n = 0; n < 8; n++) {
            mn0 = fmaxf(mn0, fmaxf(sc[n][0], sc[n][1]));
            mn1 = fmaxf(mn1, fmaxf(sc[n][2], sc[n][3]));
        }
        mn0 = fmaxf(mn0, __shfl_xor_sync(0xffffffffu, mn0, 1));
        mn0 = fmaxf(mn0, __shfl_xor_sync(0xffffffffu, mn0, 2));
        mn1 = fmaxf(mn1, __shfl_xor_sync(0xffffffffu, mn1, 1));
        mn1 = fmaxf(mn1, __shfl_xor_sync(0xffffffffu, mn1, 2));

        const float a0 = __expf(m0 - mn0);
        const float a1 = __expf(m1 - mn1);
        m0 = mn0; m1 = mn1;

        float ps0 = 0.f, ps1 = 0.f;
        #pragma unroll
        for (int n = 0; n < 8; n++) {
            sc[n][0] = __expf(sc[n][0] - mn0);
            sc[n][1] = __expf(sc[n][1] - mn0);
            sc[n][2] = __expf(sc[n][2] - mn1);
            sc[n][3] = __expf(sc[n][3] - mn1);
            ps0 += sc[n][0] + sc[n][1];
            ps1 += sc[n][2] + sc[n][3];
            o[n][0] *= a0; o[n][1] *= a0;
            o[n][2] *= a1; o[n][3] *= a1;
        }
        l0 = l0 * a0 + ps0;
        l1 = l1 * a1 + ps1;

        // ---- P -> smem (reuse K buffer; all warps done reading K) ----
        __syncthreads();
        {
            float* sP = sK;
            const int pr = warp * 16 + g;
            #pragma unroll
            for (int n = 0; n < 8; n++) {
                const int c = n * 8 + 2 * t4;
                float2 p01 = make_float2(__uint_as_float(f2tf(sc[n][0])),
                                         __uint_as_float(f2tf(sc[n][1])));
                float2 p23 = make_float2(__uint_as_float(f2tf(sc[n][2])),
                                         __uint_as_float(f2tf(sc[n][3])));
                *(float2*)(&sP[pr * LDP + c])       = p01;
                *(float2*)(&sP[(pr + 8) * LDP + c]) = p23;
            }
        }
        __syncwarp();  // P rows are warp-private; warp-level ordering suffices

        // ---- O += P @ V ----
        {
            const float* sP = sK;
            const int pr = warp * 16 + g;
            #pragma unroll
            for (int kc = 0; kc < 8; kc++) {
                uint32_t pa[4];
                pa[0] = __float_as_uint(sP[pr       * LDP + kc * 8 + t4]);
                pa[1] = __float_as_uint(sP[(pr + 8) * LDP + kc * 8 + t4]);
                pa[2] = __float_as_uint(sP[pr       * LDP + kc * 8 + t4 + 4]);
                pa[3] = __float_as_uint(sP[(pr + 8) * LDP + kc * 8 + t4 + 4]);
                #pragma unroll
                for (int n = 0; n < 8; n++) {
                    uint32_t bf[2];
                    bf[0] = __float_as_uint(sV[(n * 8 + g) * LDP + kc * 8 + t4]);
                    bf[1] = __float_as_uint(sV[(n * 8 + g) * LDP + kc * 8 + t4 + 4]);
                    mma_tf32(o[n], pa, bf, o[n]);
                }
            }
        }
    }

    // ---- epilogue: finish row sums, normalize, store ----
    l0 += __shfl_xor_sync(0xffffffffu, l0, 1);
    l0 += __shfl_xor_sync(0xffffffffu, l0, 2);
    l1 += __shfl_xor_sync(0xffffffffu, l1, 1);
    l1 += __shfl_xor_sync(0xffffffffu, l1, 2);
    const float inv0 = 1.0f / l0;
    const float inv1 = 1.0f / l1;

    const int r0 = q0 + warp * 16 + g;
    float* o_r0 = Ob + (size_t)r0 * rowstride;
    float* o_r1 = o_r0 + 8 * rowstride;
    #pragma unroll
    for (int n = 0; n < 8; n++) {
        const int c = n * 8 + 2 * t4;
        *(float2*)(o_r0 + c) = make_float2(o[n][0] * inv0, o[n][1] * inv0);
        *(float2*)(o_r1 + c) = make_float2(o[n][2] * inv1, o[n][3] * inv1);
    }
}

extern "C" void kernel_launch(void* const* d_in, const int* in_sizes, int n_in,
                              void* d_out, int out_size) {
    (void)in_sizes; (void)n_in; (void)out_size;
    const float* q = (const float*)d_in[0];
    const float* k = (const float*)d_in[1];
    const float* v = (const float*)d_in[2];
    float* out = (float*)d_out;
    dim3 grid(SEQLEN / BM, NHEADS, BATCH);
    fa_tf32_kernel<<<grid, NTHREADS>>>(q, k, v, out);
}

// round 5
// speedup vs baseline: 1.6557x; 1.6557x over previous
#include <cuda_runtime.h>
#include <math.h>
#include <stdint.h>

// Causal SDPA, flash-attention-2, TF32 mma.sync, smem-wavefront-optimized.
// B=2, S=4096, NH=16, HD=64, fp32 in/out. Layout [B, S, NH, HD].
//
// Key tricks vs R4 kernel:
//  * P (probabilities) never touches smem: the kv axis of P@V's contraction is
//    relabeled so the S-accumulator registers ARE the A fragments
//    (pa = {sc[0], sc[2], sc[1], sc[3]}), with V's B fragment reading the
//    matching kv rows (2t4, 2t4+1) from naturally-laid-out sV.
//  * V staged un-transposed (STS.128 conflict-free) instead of the 8-way
//    conflicted transpose stores.
//  * K fragments loaded as LDS.64 by permuting the hd contraction axis on the
//    Q side only (k-pos p <-> actual hd 2(p&3)+(p>>2)); LDK=72 makes the
//    float2 loads bank-conflict-free.
//  * exp via ex2.approx with log2(e) folded into the Q scale.
#define BATCH    2
#define SEQLEN   4096
#define NHEADS   16
#define HDIM     64
#define BM       64
#define BN       64
#define LDK      72   // sK row stride (floats): conflict-free LDS.64 frags
#define LDV      68   // sV row stride (floats): conflict-free LDS.32 frags
#define NTHREADS 128

__device__ __forceinline__ uint32_t f2tf(float f) {
    uint32_t r;
    asm("cvt.rna.tf32.f32 %0, %1;" : "=r"(r) : "f"(f));
    return r;
}

__device__ __forceinline__ float ex2(float x) {
    float r;
    asm("ex2.approx.f32 %0, %1;" : "=f"(r) : "f"(x));
    return r;
}

__device__ __forceinline__ void mma_tf32(float* d, const uint32_t* a,
                                         const uint32_t* b, const float* c) {
    asm("mma.sync.aligned.m16n8k8.row.col.f32.tf32.tf32.f32 "
        "{%0,%1,%2,%3}, {%4,%5,%6,%7}, {%8,%9}, {%10,%11,%12,%13};\n"
        : "=f"(d[0]), "=f"(d[1]), "=f"(d[2]), "=f"(d[3])
        : "r"(a[0]), "r"(a[1]), "r"(a[2]), "r"(a[3]),
          "r"(b[0]), "r"(b[1]),
          "f"(c[0]), "f"(c[1]), "f"(c[2]), "f"(c[3]));
}

__global__ void __launch_bounds__(NTHREADS, 3)
fa_tf32_kernel(const float* __restrict__ Q, const float* __restrict__ K,
               const float* __restrict__ V, float* __restrict__ O)
{
    __shared__ float sK[BN * LDK];    // K tile [kv][hd], natural hd order
    __shared__ float sV[BN * LDV];    // V tile [kv][hd], natural order

    const int qt   = (SEQLEN / BM - 1) - (int)blockIdx.x;  // heavy tiles first
    const int h    = blockIdx.y;
    const int b    = blockIdx.z;
    const int tid  = threadIdx.x;
    const int warp = tid >> 5;
    const int lane = tid & 31;
    const int g    = lane >> 2;
    const int t4   = lane & 3;

    const int q0 = qt * BM;
    const size_t rowstride = (size_t)NHEADS * HDIM;
    const size_t base = (size_t)b * SEQLEN * rowstride + (size_t)h * HDIM;
    const float* Qb = Q + base;
    const float* Kb = K + base;
    const float* Vb = V + base;
    float*       Ob = O + base;

    // ---- Q fragments, hd-permuted so k-pos p <-> actual hd 2(p&3)+(p>>2) ----
    // a[0]=(row g,   k=t4)   -> Q[hd 8kc+2t4]
    // a[2]=(row g,   k=t4+4) -> Q[hd 8kc+2t4+1]
    // Scale folds 1/sqrt(64) and log2(e) (softmax done in base-2).
    uint32_t qa[8][4];
    {
        const int r0 = q0 + warp * 16 + g;
        const float* q_r0 = Qb + (size_t)r0 * rowstride;
        const float* q_r1 = q_r0 + 8 * rowstride;
        const float scale = 0.125f * 1.4426950408889634f;
        #pragma unroll
        for (int kc = 0; kc < 8; kc++) {
            const int c = kc * 8 + 2 * t4;
            float2 x0 = *(const float2*)(q_r0 + c);
            float2 x1 = *(const float2*)(q_r1 + c);
            qa[kc][0] = f2tf(x0.x * scale);
            qa[kc][1] = f2tf(x1.x * scale);
            qa[kc][2] = f2tf(x0.y * scale);
            qa[kc][3] = f2tf(x1.y * scale);
        }
    }

    float m0 = -1e30f, m1 = -1e30f;
    float l0 = 0.f,    l1 = 0.f;
    float o[8][4];
    #pragma unroll
    for (int n = 0; n < 8; n++) { o[n][0] = o[n][1] = o[n][2] = o[n][3] = 0.f; }

    for (int kt = 0; kt <= qt; kt++) {
        const int k0 = kt * BN;
        __syncthreads();  // previous tile's frag reads done before restaging

        // ---- stage K and V (both natural layout, STS.128, tf32-rounded) ----
        {
            const float* Kt = Kb + (size_t)k0 * rowstride;
            const float* Vt = Vb + (size_t)k0 * rowstride;
            #pragma unroll
            for (int j = 0; j < 8; j++) {
                const int f  = tid + NTHREADS * j;   // 1024 float4s
                const int rw = f >> 4;
                const int c4 = (f & 15) << 2;
                float4 kk = *(const float4*)(Kt + (size_t)rw * rowstride + c4);
                kk.x = __uint_as_float(f2tf(kk.x));
                kk.y = __uint_as_float(f2tf(kk.y));
                kk.z = __uint_as_float(f2tf(kk.z));
                kk.w = __uint_as_float(f2tf(kk.w));
                *(float4*)(&sK[rw * LDK + c4]) = kk;
                float4 vv = *(const float4*)(Vt + (size_t)rw * rowstride + c4);
                vv.x = __uint_as_float(f2tf(vv.x));
                vv.y = __uint_as_float(f2tf(vv.y));
                vv.z = __uint_as_float(f2tf(vv.z));
                vv.w = __uint_as_float(f2tf(vv.w));
                *(float4*)(&sV[rw * LDV + c4]) = vv;
            }
        }
        __syncthreads();

        // ---- S = Qs @ K^T: B-frag k-pos {t4, t4+4} -> smem cols {2t4, 2t4+1} ----
        float sc[8][4];
        #pragma unroll
        for (int n = 0; n < 8; n++) { sc[n][0] = sc[n][1] = sc[n][2] = sc[n][3] = 0.f; }
        #pragma unroll
        for (int kc = 0; kc < 8; kc++) {
            #pragma unroll
            for (int n = 0; n < 8; n++) {
                float2 kf = *(const float2*)(&sK[(n * 8 + g) * LDK + kc * 8 + 2 * t4]);
                uint32_t bf[2];
                bf[0] = __float_as_uint(kf.x);
                bf[1] = __float_as_uint(kf.y);
                mma_tf32(sc[n], qa[kc], bf, sc[n]);
            }
        }

        // ---- causal mask on diagonal tile (acc col 2t4+e <-> kv 8n+2t4+e) ----
        if (kt == qt) {
            const int r0 = q0 + warp * 16 + g;
            #pragma unroll
            for (int n = 0; n < 8; n++) {
                const int c = k0 + n * 8 + 2 * t4;
                if (c     > r0)     sc[n][0] = -1e30f;
                if (c + 1 > r0)     sc[n][1] = -1e30f;
                if (c     > r0 + 8) sc[n][2] = -1e30f;
                if (c + 1 > r0 + 8) sc[n][3] = -1e30f;
            }
        }

        // ---- online softmax (base-2; rows g, g+8) ----
        float mn0 = m0, mn1 = m1;
        #pragma unroll
        for (int n = 0; n < 8; n++) {
            mn0 = fmaxf(mn0, fmaxf(sc[n][0], sc[n][1]));
            mn1 = fmaxf(mn1, fmaxf(sc[n][2], sc[n][3]));
        }
        mn0 = fmaxf(mn0, __shfl_xor_sync(0xffffffffu, mn0, 1));
        mn0 = fmaxf(mn0, __shfl_xor_sync(0xffffffffu, mn0, 2));
        mn1 = fmaxf(mn1, __shfl_xor_sync(0xffffffffu, mn1, 1));
        mn1 = fmaxf(mn1, __shfl_xor_sync(0xffffffffu, mn1, 2));

        const float a0 = ex2(m0 - mn0);
        const float a1 = ex2(m1 - mn1);
        m0 = mn0; m1 = mn1;

        float ps0 = 0.f, ps1 = 0.f;
        #pragma unroll
        for (int n = 0; n < 8; n++) {
            sc[n][0] = ex2(sc[n][0] - mn0);
            sc[n][1] = ex2(sc[n][1] - mn0);
            sc[n][2] = ex2(sc[n][2] - mn1);
            sc[n][3] = ex2(sc[n][3] - mn1);
            ps0 += sc[n][0] + sc[n][1];
            ps1 += sc[n][2] + sc[n][3];
            o[n][0] *= a0; o[n][1] *= a0;
            o[n][2] *= a1; o[n][3] *= a1;
        }
        l0 = l0 * a0 + ps0;
        l1 = l1 * a1 + ps1;

        // ---- O += P @ V directly from accumulator registers ----
        // A-slot k-pos p means kv 8kc+2(p&3)+(p>>2):
        //   pa = {sc[kc][0], sc[kc][2], sc[kc][1], sc[kc][3]}
        // B-slot k-pos {t4, t4+4} -> sV kv rows {8kc+2t4, 8kc+2t4+1}.
        #pragma unroll
        for (int kc = 0; kc < 8; kc++) {
            uint32_t pa[4];
            pa[0] = f2tf(sc[kc][0]);
            pa[1] = f2tf(sc[kc][2]);
            pa[2] = f2tf(sc[kc][1]);
            pa[3] = f2tf(sc[kc][3]);
            const float* v0 = &sV[(kc * 8 + 2 * t4) * LDV + g];
            const float* v1 = v0 + LDV;
            #pragma unroll
            for (int n = 0; n < 8; n++) {
                uint32_t bf[2];
                bf[0] = __float_as_uint(v0[n * 8]);
                bf[1] = __float_as_uint(v1[n * 8]);
                mma_tf32(o[n], pa, bf, o[n]);
            }
        }
    }

    // ---- epilogue ----
    l0 += __shfl_xor_sync(0xffffffffu, l0, 1);
    l0 += __shfl_xor_sync(0xffffffffu, l0, 2);
    l1 += __shfl_xor_sync(0xffffffffu, l1, 1);
    l1 += __shfl_xor_sync(0xffffffffu, l1, 2);
    const float inv0 = 1.0f / l0;
    const float inv1 = 1.0f / l1;

    const int r0 = q0 + warp * 16 + g;
    float* o_r0 = Ob + (size_t)r0 * rowstride;
    float* o_r1 = o_r0 + 8 * rowstride;
    #pragma unroll
    for (int n = 0; n < 8; n++) {
        const int c = n * 8 + 2 * t4;
        *(float2*)(o_r0 + c) = make_float2(o[n][0] * inv0, o[n][1] * inv0);
        *(float2*)(o_r1 + c) = make_float2(o[n][2] * inv1, o[n][3] * inv1);
    }
}

extern "C" void kernel_launch(void* const* d_in, const int* in_sizes, int n_in,
                              void* d_out, int out_size) {
    (void)in_sizes; (void)n_in; (void)out_size;
    const float* q = (const float*)d_in[0];
    const float* k = (const float*)d_in[1];
    const float* v = (const float*)d_in[2];
    float* out = (float*)d_out;
    dim3 grid(SEQLEN / BM, NHEADS, BATCH);
    fa_tf32_kernel<<<grid, NTHREADS>>>(q, k, v, out);
}